// round 10
// baseline (speedup 1.0000x reference)
#include <cuda_runtime.h>

#define FULLMASK 0xFFFFFFFFu

__device__ float g_recon[8192];
__device__ unsigned g_count = 0;

// Four batches per warp (8-lane segments). Lane sl (0..7) owns states 8sl+1..8sl+8.
// Delete-chain cross-lane scan done as a precomputed-weight matvec over SMEM
// broadcasts (time-invariant ratios) instead of serial shuffles.
// Linear space + power-of-two renorm every 8 steps. Fused KLD + tailgate mean.
__global__ __launch_bounds__(256, 1)
void phmm_fused_kernel(const int* __restrict__ x,
                       const float* __restrict__ a,
                       const float* __restrict__ e,
                       const float* __restrict__ mus,
                       const float* __restrict__ lvs,
                       float* __restrict__ out, int B, int E)
{
    __shared__ float es_sm[256 * 36];    // [tid][sym][8 rows], stride 36 words
    __shared__ float p8_sm[2][256];      // double-buffered scan operands

    const int tid   = threadIdx.x;
    const int warp  = (int)((blockIdx.x * blockDim.x + tid) >> 5);
    const int lane  = tid & 31;
    const int sl    = lane & 7;
    const int batch = 4 * warp + (lane >> 3);
    const int bc    = (batch < B) ? batch : (B - 1);   // clamp; final write guarded

    // ---- KLD for this segment's batch ----
    float kterm = 0.f;
    for (int j = sl; j < E; j += 8) {
        float m_ = mus[(size_t)bc * E + j];
        float v  = lvs[(size_t)bc * E + j];
        kterm += 1.f + v - m_ * m_ - __expf(v);
    }
    #pragma unroll
    for (int d = 4; d > 0; d >>= 1) kterm += __shfl_xor_sync(FULLMASK, kterm, d, 8);

    const float* ab  = a + (size_t)bc * 455;   // (65, 7)
    const float* ebp = e + (size_t)bc * 256;   // (64, 4)
    const int r0 = sl * 8;

    // enum: M2M=0, M2I=1, M2D=2, I2M=3, I2I=4, D2M=5, D2D=6
    float TMM[8], TIM[8], TDM[8], TMD[8], TDD[8], TMIq[8], TIIq[8];
    #pragma unroll
    for (int c = 0; c < 8; c++) {
        const float* rw = ab + (r0 + c) * 7;
        TMM[c]  = __expf(rw[0]);
        TMIq[c] = 0.25f * __expf(rw[1]);
        TMD[c]  = __expf(rw[2]);
        TIM[c]  = __expf(rw[3]);
        TIIq[c] = 0.25f * __expf(rw[4]);
        TDM[c]  = __expf(rw[5]);
        TDD[c]  = __expf(rw[6]);
    }
    float TMI8 = 0.25f * __expf(ab[(r0 + 8) * 7 + 1]);
    float TII8 = 0.25f * __expf(ab[(r0 + 8) * 7 + 4]);
    float TMMf = __expf(ab[64 * 7 + 0]);
    float TIMf = __expf(ab[64 * 7 + 3]);
    float TDMf = __expf(ab[64 * 7 + 5]);

    // boundary: fD[0] == 0 always -> zero its multipliers on segment lane 0
    if (sl == 0) { TDM[0] = 0.f; TDD[0] = 0.f; }

    // emissions -> private SMEM slots: es_sm[tid*36 + sym*8 + c]
    {
        float* myes = es_sm + tid * 36;
        #pragma unroll
        for (int c = 0; c < 8; c++) {
            float4 er = *reinterpret_cast<const float4*>(ebp + (r0 + c) * 4);
            myes[0 * 8 + c] = __expf(er.x);
            myes[1 * 8 + c] = __expf(er.y);
            myes[2 * 8 + c] = __expf(er.z);
            myes[3 * 8 + c] = __expf(er.w);
        }
    }

    // Q prefixes: Q[c] = prod TDD[0..c-1] (time-invariant)
    float Q[8];
    Q[1] = TDD[0];
    #pragma unroll
    for (int c = 2; c < 8; c++) Q[c] = Q[c - 1] * TDD[c - 1];
    float Rseg = Q[7] * TDD[7];

    // ---- scan weights: Au_j = sum_i WA[i] * P8_i, WA[i] = prod Rseg[i+1..j] ----
    float Rall[8];
    #pragma unroll
    for (int i = 0; i < 8; i++) Rall[i] = __shfl_sync(FULLMASK, Rseg, i, 8);
    float WA[8];
    WA[7] = (sl == 7) ? 1.f : 0.f;
    #pragma unroll
    for (int i = 6; i >= 0; i--)
        WA[i] = (i == sl) ? 1.f : Rall[i + 1] * WA[i + 1];

    // symbol packing: lane sl holds the 16-symbol word for time group sl
    unsigned word;
    {
        const int4* xv = reinterpret_cast<const int4*>(x + (size_t)bc * 128) + sl * 4;
        int4 q0 = xv[0], q1 = xv[1], q2 = xv[2], q3 = xv[3];
        word =  (unsigned)q0.x        | ((unsigned)q0.y << 2)  | ((unsigned)q0.z << 4)  | ((unsigned)q0.w << 6)
             | ((unsigned)q1.x << 8)  | ((unsigned)q1.y << 10) | ((unsigned)q1.z << 12) | ((unsigned)q1.w << 14)
             | ((unsigned)q2.x << 16) | ((unsigned)q2.y << 18) | ((unsigned)q2.z << 20) | ((unsigned)q2.w << 22)
             | ((unsigned)q3.x << 24) | ((unsigned)q3.y << 26) | ((unsigned)q3.z << 28) | ((unsigned)q3.w << 30);
    }

    // ---- state ----
    float fMo[8], fI[8], fD[8];
    float fM8 = 0.f, fI8 = 0.f, FD8;
    #pragma unroll
    for (int c = 0; c < 8; c++) { fMo[c] = 0.f; fI[c] = 0.f; }
    fMo[0] = (sl == 0) ? 1.f : 0.f;          // fM0[0] = 1 (linear)
    int expAcc = 0;

    const int segbase = tid & ~7;

    // initial delete chain (only state 0 carries mass) — buffer 1
    {
        float u[9];
        u[1] = TMD[0] * fMo[0];
        #pragma unroll
        for (int c = 2; c <= 8; c++) u[c] = TDD[c - 1] * u[c - 1];
        p8_sm[1][tid] = u[8];
        __syncwarp();
        const float4* pv = reinterpret_cast<const float4*>(&p8_sm[1][segbase]);
        float4 pa = pv[0], pb = pv[1];
        float P[8] = {pa.x, pa.y, pa.z, pa.w, pb.x, pb.y, pb.z, pb.w};
        float Au = 0.f;
        #pragma unroll
        for (int i = 0; i < 8; i++) Au = fmaf(WA[i], P[i], Au);
        float Pex = __shfl_up_sync(FULLMASK, Au, 1, 8);
        if (sl == 0) Pex = 0.f;
        fD[0] = Pex;
        #pragma unroll
        for (int c = 1; c < 8; c++) fD[c] = fmaf(Q[c], Pex, u[c]);
        FD8 = Au;
    }

    const float* myes = es_sm + tid * 36;

    // ---- main loop: 8 groups x 16 steps, renorm every 8 steps ----
    for (int w = 0; w < 8; w++) {
        unsigned pw = __shfl_sync(FULLMASK, word, w, 8);
        #pragma unroll
        for (int s = 0; s < 16; s++) {
            int sym = (int)((pw >> (2 * s)) & 3u);
            const float4* ep = reinterpret_cast<const float4*>(myes + sym * 8);
            float4 eA = ep[0], eB = ep[1];
            float es_[8] = {eA.x, eA.y, eA.z, eA.w, eB.x, eB.y, eB.z, eB.w};

            // M update: nf[c+1] = es_c * (TMM*fM + TIM*fI + TDM*fD) at row c
            float nf[9];
            #pragma unroll
            for (int c = 0; c < 8; c++)
                nf[c + 1] = es_[c] * fmaf(TMM[c], fMo[c],
                                    fmaf(TIM[c], fI[c], TDM[c] * fD[c]));

            // I update (own rows, uses OLD fM)
            #pragma unroll
            for (int c = 0; c < 8; c++)
                fI[c] = fmaf(TMIq[c], fMo[c], TIIq[c] * fI[c]);
            fI8 = fmaf(TMI8, fM8, TII8 * fI8);
            fM8 = nf[8];

            // delete chain on NEW fM: local serial chain -> SMEM broadcast matvec
            float pN = __shfl_up_sync(FULLMASK, nf[8], 1, 8);
            if (sl == 0) pN = 0.f;           // fM_new[0] = 0 for l >= 1
            float u[9];
            u[1] = TMD[0] * pN;
            #pragma unroll
            for (int c = 2; c <= 8; c++)
                u[c] = fmaf(TDD[c - 1], u[c - 1], TMD[c - 1] * nf[c - 1]);

            p8_sm[s & 1][tid] = u[8];
            __syncwarp();
            const float4* pv = reinterpret_cast<const float4*>(&p8_sm[s & 1][segbase]);
            float4 pa = pv[0], pb = pv[1];
            float P[8] = {pa.x, pa.y, pa.z, pa.w, pb.x, pb.y, pb.z, pb.w};
            float Au0 = 0.f, Au1 = 0.f;
            #pragma unroll
            for (int i = 0; i < 4; i++) {
                Au0 = fmaf(WA[i], P[i], Au0);
                Au1 = fmaf(WA[i + 4], P[i + 4], Au1);
            }
            float Au = Au0 + Au1;
            float Pex = __shfl_up_sync(FULLMASK, Au, 1, 8);
            if (sl == 0) Pex = 0.f;
            fD[0] = Pex;
            #pragma unroll
            for (int c = 1; c < 8; c++) fD[c] = fmaf(Q[c], Pex, u[c]);
            FD8 = Au;

            // rotate M state (pure renaming)
            fMo[0] = pN;
            #pragma unroll
            for (int c = 1; c < 8; c++) fMo[c] = nf[c];

            if (s == 7 || s == 15) {   // renorm every 8 steps
                float m = fmaxf(fI8, FD8);
                #pragma unroll
                for (int c = 0; c < 8; c++) {
                    m = fmaxf(m, fMo[c]);
                    m = fmaxf(m, fI[c]);
                    m = fmaxf(m, fD[c]);
                }
                m = fmaxf(m, fM8);
                #pragma unroll
                for (int d = 4; d > 0; d >>= 1)
                    m = fmaxf(m, __shfl_xor_sync(FULLMASK, m, d, 8));
                int eb = (__float_as_int(m) >> 23) & 255;
                eb = max(1, min(253, eb));
                float sc = __int_as_float((254 - eb) << 23);  // 2^(127-eb)
                expAcc += eb - 127;
                #pragma unroll
                for (int c = 0; c < 8; c++) {
                    fMo[c] *= sc; fI[c] *= sc; fD[c] *= sc;
                }
                fM8 *= sc; fI8 *= sc; FD8 *= sc;
            }
        }
    }

    if (sl == 7 && batch < B) {
        float S = fmaf(TMMf, fM8, fmaf(TIMf, fI8, TDMf * FD8));
        S = fmaxf(S, 1e-37f);
        g_recon[batch] = -(logf(S) + (float)expAcc * 0.69314718055994530942f)
                         - 0.5f * kterm;
    }

    // ---- deterministic fused final reduction (threadfence tailgate) ----
    __syncthreads();                      // order this block's g_recon stores
    __shared__ unsigned sIsLast;
    if (tid == 0) {
        __threadfence();                  // release: publish g_recon writes
        unsigned v = atomicAdd(&g_count, 1u);
        sIsLast = (v == gridDim.x - 1) ? 1u : 0u;
    }
    __syncthreads();
    if (sIsLast) {
        __threadfence();                  // acquire: see all g_recon writes
        const float4* g4 = reinterpret_cast<const float4*>(g_recon);
        int n4 = B >> 2;                  // 1024 for B=4096
        float p[4];
        #pragma unroll
        for (int k = 0; k < 4; k++) p[k] = 0.f;
        for (int i0 = tid; i0 < n4; i0 += 256 * 4) {
            #pragma unroll
            for (int k = 0; k < 4; k++) {
                int i = i0 + k * 256;
                if (i < n4) {
                    float4 v = g4[i];
                    p[k] += (v.x + v.y) + (v.z + v.w);
                }
            }
        }
        float ssum = (p[0] + p[1]) + (p[2] + p[3]);
        #pragma unroll
        for (int d = 16; d > 0; d >>= 1)
            ssum += __shfl_xor_sync(FULLMASK, ssum, d);
        __shared__ float sh[8];
        if ((tid & 31) == 0) sh[tid >> 5] = ssum;
        __syncthreads();
        if (tid == 0) {
            float tot = ((sh[0] + sh[1]) + (sh[2] + sh[3]))
                      + ((sh[4] + sh[5]) + (sh[6] + sh[7]));
            out[0] = tot / (float)B;
            g_count = 0;                  // reset for next graph replay
        }
    }
}

extern "C" void kernel_launch(void* const* d_in, const int* in_sizes, int n_in,
                              void* d_out, int out_size)
{
    const int*   x   = (const int*)d_in[0];     // (B, 128) int32
    const float* a   = (const float*)d_in[1];   // (B, 65, 7)
    const float* e   = (const float*)d_in[2];   // (B, 64, 4)
    const float* mus = (const float*)d_in[3];   // (B, E)
    const float* lvs = (const float*)d_in[4];   // (B, E)

    int B = in_sizes[1] / 455;                  // (K+1)*7 = 455
    if (B > 8192) B = 8192;
    int E = in_sizes[3] / B;

    int blocks = (B + 31) / 32;                 // 32 batches per 256-thread block
    phmm_fused_kernel<<<blocks, 256>>>(x, a, e, mus, lvs, (float*)d_out, B, E);
}

// round 11
// speedup vs baseline: 1.0164x; 1.0164x over previous
#include <cuda_runtime.h>

#define FULLMASK 0xFFFFFFFFu

__device__ float g_recon[8192];
__device__ unsigned g_count = 0;

// Four batches per 32-thread block (one warp). Lane sl (0..7) of each 8-lane
// segment owns states 8sl+1..8sl+8. No in-loop shuffles: delete-chain scan is
// a precomputed-weight matvec over SMEM-published {u'8, m8}; pN via LDS.32.
// Linear space + power-of-two renorm every 8 steps. Fused KLD + tailgate mean.
__global__ __launch_bounds__(32)
void phmm_fused_kernel(const int* __restrict__ x,
                       const float* __restrict__ a,
                       const float* __restrict__ e,
                       const float* __restrict__ mus,
                       const float* __restrict__ lvs,
                       float* __restrict__ out, int B, int E)
{
    __shared__ __align__(16) float es_sm[32 * 36];  // [tid][sym][8 rows]
    __shared__ __align__(16) float u8b[2][32];      // published u'8 (double buf)
    __shared__ __align__(16) float m8b[2][32];      // published nf[8]

    const int tid   = threadIdx.x;                  // 0..31
    const int sl    = tid & 7;
    const int seg   = tid >> 3;                     // 0..3
    const int batch = blockIdx.x * 4 + seg;
    const int bc    = (batch < B) ? batch : (B - 1);

    // ---- KLD for this segment's batch ----
    float kterm = 0.f;
    for (int j = sl; j < E; j += 8) {
        float m_ = mus[(size_t)bc * E + j];
        float v  = lvs[(size_t)bc * E + j];
        kterm += 1.f + v - m_ * m_ - __expf(v);
    }
    #pragma unroll
    for (int d = 4; d > 0; d >>= 1) kterm += __shfl_xor_sync(FULLMASK, kterm, d, 8);

    const float* ab  = a + (size_t)bc * 455;   // (65, 7)
    const float* ebp = e + (size_t)bc * 256;   // (64, 4)
    const int r0 = sl * 8;

    // enum: M2M=0, M2I=1, M2D=2, I2M=3, I2I=4, D2M=5, D2D=6
    float TMM[8], TIM[8], TDM[8], TMD[8], TDD[8], TMIq[8], TIIq[8];
    #pragma unroll
    for (int c = 0; c < 8; c++) {
        const float* rw = ab + (r0 + c) * 7;
        TMM[c]  = __expf(rw[0]);
        TMIq[c] = 0.25f * __expf(rw[1]);
        TMD[c]  = __expf(rw[2]);
        TIM[c]  = __expf(rw[3]);
        TIIq[c] = 0.25f * __expf(rw[4]);
        TDM[c]  = __expf(rw[5]);
        TDD[c]  = __expf(rw[6]);
    }
    float TMI8 = 0.25f * __expf(ab[(r0 + 8) * 7 + 1]);
    float TII8 = 0.25f * __expf(ab[(r0 + 8) * 7 + 4]);
    float TMMf = __expf(ab[64 * 7 + 0]);
    float TIMf = __expf(ab[64 * 7 + 3]);
    float TDMf = __expf(ab[64 * 7 + 5]);

    // boundary: fD[0] == 0 always -> zero its multipliers on segment lane 0
    // (TMD[0] = M2D out of match state 0 is real and stays)
    if (sl == 0) { TDM[0] = 0.f; TDD[0] = 0.f; }

    // emissions -> private SMEM slots
    {
        float* myes = es_sm + tid * 36;
        #pragma unroll
        for (int c = 0; c < 8; c++) {
            float4 er = *reinterpret_cast<const float4*>(ebp + (r0 + c) * 4);
            myes[0 * 8 + c] = __expf(er.x);
            myes[1 * 8 + c] = __expf(er.y);
            myes[2 * 8 + c] = __expf(er.z);
            myes[3 * 8 + c] = __expf(er.w);
        }
    }

    // Q[c]  = prod TDD[0..c-1]          (coef of Pex in fD[c])
    // Qp[c] = TMD[0]*prod TDD[1..c-1]   (coef of pN  in u[c])
    float Q[8], Qp[8];
    Q[1] = TDD[0]; Qp[1] = TMD[0];
    #pragma unroll
    for (int c = 2; c < 8; c++) {
        Q[c]  = Q[c - 1] * TDD[c - 1];
        Qp[c] = Qp[c - 1] * TDD[c - 1];
    }
    float Qp8  = Qp[7] * TDD[7];
    float Rseg = Q[7] * TDD[7];          // full lane ratio (0 on sl==0)

    // broadcasts for weight construction (one-time)
    float Rall[8], Qpall[8];
    #pragma unroll
    for (int i = 0; i < 8; i++) {
        Rall[i]  = __shfl_sync(FULLMASK, Rseg, i, 8);
        Qpall[i] = __shfl_sync(FULLMASK, Qp8,  i, 8);
    }
    // Pex_j = Au_{j-1} = sum_i WPA[i]*u'8_i + sum_i WPB[i]*m8_i
    float WPA[8], WPB[8];
    {
        float acc = 0.f;
        #pragma unroll
        for (int i = 7; i >= 0; i--) {
            if (i == sl - 1) acc = 1.f;
            else             acc = Rall[(i + 1) & 7] * acc;
            WPA[i] = acc;
        }
        #pragma unroll
        for (int i = 0; i < 7; i++) WPB[i] = WPA[i + 1] * Qpall[i + 1];
        WPB[7] = 0.f;
    }

    // symbol packing: lane sl holds the 16-symbol word for time group sl
    unsigned word;
    {
        const int4* xv = reinterpret_cast<const int4*>(x + (size_t)bc * 128) + sl * 4;
        int4 q0 = xv[0], q1 = xv[1], q2 = xv[2], q3 = xv[3];
        word =  (unsigned)q0.x        | ((unsigned)q0.y << 2)  | ((unsigned)q0.z << 4)  | ((unsigned)q0.w << 6)
             | ((unsigned)q1.x << 8)  | ((unsigned)q1.y << 10) | ((unsigned)q1.z << 12) | ((unsigned)q1.w << 14)
             | ((unsigned)q2.x << 16) | ((unsigned)q2.y << 18) | ((unsigned)q2.z << 20) | ((unsigned)q2.w << 22)
             | ((unsigned)q3.x << 24) | ((unsigned)q3.y << 26) | ((unsigned)q3.z << 28) | ((unsigned)q3.w << 30);
    }

    // ---- state ----
    float fMo[8], fI[8], fD[8];
    float fM8 = 0.f, fI8 = 0.f, FD8;
    #pragma unroll
    for (int c = 0; c < 8; c++) { fMo[c] = 0.f; fI[c] = 0.f; }
    fMo[0] = (sl == 0) ? 1.f : 0.f;          // fM0[0] = 1 (linear)
    int expAcc = 0;

    const int pidx = (tid == 0) ? 0 : (tid - 1);   // left-neighbor slot (clamped)

    // ---- initial delete chain (only state 0 carries mass) ----
    {
        float u8i = Qp8 * fMo[0];            // u[8] with pN_init folded in
        u8b[1][tid] = u8i;
        m8b[1][tid] = 0.f;
        __syncwarp();
        const float4* Uv = reinterpret_cast<const float4*>(&u8b[1][seg * 8]);
        float4 Ua = Uv[0], Ub = Uv[1];
        float a0 = WPA[0] * Ua.x; a0 = fmaf(WPA[2], Ua.z, a0);
        a0 = fmaf(WPA[4], Ub.x, a0); a0 = fmaf(WPA[6], Ub.z, a0);
        float a1 = WPA[1] * Ua.y; a1 = fmaf(WPA[3], Ua.w, a1);
        a1 = fmaf(WPA[5], Ub.y, a1); a1 = fmaf(WPA[7], Ub.w, a1);
        float Pex = a0 + a1;
        FD8 = fmaf(Rseg, Pex, u8i);
        fD[0] = Pex;
        #pragma unroll
        for (int c = 1; c < 8; c++) fD[c] = fmaf(Q[c], Pex, Qp[c] * fMo[0]);
    }

    const float* myes = es_sm + tid * 36;

    // ---- main loop: 8 groups x 16 steps, renorm every 8 steps ----
    for (int w = 0; w < 8; w++) {
        unsigned pw = __shfl_sync(FULLMASK, word, w, 8);
        #pragma unroll
        for (int s = 0; s < 16; s++) {
            int sym = (int)((pw >> (2 * s)) & 3u);
            const float4* ep = reinterpret_cast<const float4*>(myes + sym * 8);
            float4 eA = ep[0], eB = ep[1];
            float es_[8] = {eA.x, eA.y, eA.z, eA.w, eB.x, eB.y, eB.z, eB.w};

            // M update: nf[c+1] = es_c * (TMM*fM + TIM*fI + TDM*fD) at row c
            float nf[9];
            #pragma unroll
            for (int c = 0; c < 8; c++)
                nf[c + 1] = es_[c] * fmaf(TMM[c], fMo[c],
                                    fmaf(TIM[c], fI[c], TDM[c] * fD[c]));

            // I update (own rows, uses OLD fM)
            #pragma unroll
            for (int c = 0; c < 8; c++)
                fI[c] = fmaf(TMIq[c], fMo[c], TIIq[c] * fI[c]);
            fI8 = fmaf(TMI8, fM8, TII8 * fI8);
            fM8 = nf[8];

            // pN-free local delete chain u'[c]
            float up[9];
            up[2] = TMD[1] * nf[1];
            #pragma unroll
            for (int c = 3; c <= 8; c++)
                up[c] = fmaf(TDD[c - 1], up[c - 1], TMD[c - 1] * nf[c - 1]);

            const int b = s & 1;
            u8b[b][tid] = up[8];
            m8b[b][tid] = nf[8];
            __syncwarp();
            const float4* Uv = reinterpret_cast<const float4*>(&u8b[b][seg * 8]);
            const float4* Mv = reinterpret_cast<const float4*>(&m8b[b][seg * 8]);
            float4 Ua = Uv[0], Ub = Uv[1];
            float4 Ma = Mv[0], Mb = Mv[1];
            float pNl = m8b[b][pidx];
            float pN  = (sl == 0) ? 0.f : pNl;   // fM_new[0] = 0 for l >= 1

            float a0 = WPA[0] * Ua.x; a0 = fmaf(WPA[2], Ua.z, a0);
            a0 = fmaf(WPA[4], Ub.x, a0); a0 = fmaf(WPA[6], Ub.z, a0);
            float a1 = WPA[1] * Ua.y; a1 = fmaf(WPA[3], Ua.w, a1);
            a1 = fmaf(WPA[5], Ub.y, a1); a1 = fmaf(WPA[7], Ub.w, a1);
            float b0 = WPB[0] * Ma.x; b0 = fmaf(WPB[2], Ma.z, b0);
            b0 = fmaf(WPB[4], Mb.x, b0); b0 = fmaf(WPB[6], Mb.z, b0);
            float b1 = WPB[1] * Ma.y; b1 = fmaf(WPB[3], Ma.w, b1);
            b1 = fmaf(WPB[5], Mb.y, b1);
            float Pex = (a0 + a1) + (b0 + b1);

            FD8 = fmaf(Rseg, Pex, fmaf(Qp8, pN, up[8]));
            fD[0] = Pex;
            fD[1] = fmaf(Q[1], Pex, Qp[1] * pN);          // u'[1] = 0
            #pragma unroll
            for (int c = 2; c < 8; c++)
                fD[c] = fmaf(Q[c], Pex, fmaf(Qp[c], pN, up[c]));

            // rotate M state (pure renaming)
            fMo[0] = pN;
            #pragma unroll
            for (int c = 1; c < 8; c++) fMo[c] = nf[c];

            if (s == 7 || s == 15) {   // renorm every 8 steps
                float m = fmaxf(fI8, FD8);
                #pragma unroll
                for (int c = 0; c < 8; c++) {
                    m = fmaxf(m, fMo[c]);
                    m = fmaxf(m, fI[c]);
                    m = fmaxf(m, fD[c]);
                }
                m = fmaxf(m, fM8);
                #pragma unroll
                for (int d = 4; d > 0; d >>= 1)
                    m = fmaxf(m, __shfl_xor_sync(FULLMASK, m, d, 8));
                int eb = (__float_as_int(m) >> 23) & 255;
                eb = max(1, min(253, eb));
                float sc = __int_as_float((254 - eb) << 23);  // 2^(127-eb)
                expAcc += eb - 127;
                #pragma unroll
                for (int c = 0; c < 8; c++) {
                    fMo[c] *= sc; fI[c] *= sc; fD[c] *= sc;
                }
                fM8 *= sc; fI8 *= sc; FD8 *= sc;
            }
        }
    }

    if (sl == 7 && batch < B) {
        float S = fmaf(TMMf, fM8, fmaf(TIMf, fI8, TDMf * FD8));
        S = fmaxf(S, 1e-37f);
        g_recon[batch] = -(logf(S) + (float)expAcc * 0.69314718055994530942f)
                         - 0.5f * kterm;
    }

    // ---- deterministic fused final reduction (threadfence tailgate) ----
    __syncthreads();                      // order this block's g_recon stores
    unsigned last = 0;
    if (tid == 0) {
        __threadfence();                  // release: publish g_recon writes
        last = (atomicAdd(&g_count, 1u) == (unsigned)gridDim.x - 1u) ? 1u : 0u;
    }
    last = __shfl_sync(FULLMASK, last, 0);
    if (last) {
        __threadfence();                  // acquire: see all g_recon writes
        const float4* g4 = reinterpret_cast<const float4*>(g_recon);
        int n4 = B >> 2;                  // 1024 for B=4096
        float p[8];
        #pragma unroll
        for (int k = 0; k < 8; k++) p[k] = 0.f;
        for (int i0 = tid; i0 < n4; i0 += 32 * 8) {
            #pragma unroll
            for (int k = 0; k < 8; k++) {
                int i = i0 + k * 32;
                if (i < n4) {
                    float4 v = g4[i];
                    p[k] += (v.x + v.y) + (v.z + v.w);
                }
            }
        }
        float ssum = ((p[0] + p[1]) + (p[2] + p[3])) + ((p[4] + p[5]) + (p[6] + p[7]));
        #pragma unroll
        for (int d = 16; d > 0; d >>= 1)
            ssum += __shfl_xor_sync(FULLMASK, ssum, d);
        if (tid == 0) {
            out[0] = ssum / (float)B;
            g_count = 0;                  // reset for next graph replay
        }
    }
}

extern "C" void kernel_launch(void* const* d_in, const int* in_sizes, int n_in,
                              void* d_out, int out_size)
{
    const int*   x   = (const int*)d_in[0];     // (B, 128) int32
    const float* a   = (const float*)d_in[1];   // (B, 65, 7)
    const float* e   = (const float*)d_in[2];   // (B, 64, 4)
    const float* mus = (const float*)d_in[3];   // (B, E)
    const float* lvs = (const float*)d_in[4];   // (B, E)

    int B = in_sizes[1] / 455;                  // (K+1)*7 = 455
    if (B > 8192) B = 8192;
    int E = in_sizes[3] / B;

    int blocks = (B + 3) / 4;                   // 4 batches per 32-thread block
    phmm_fused_kernel<<<blocks, 32>>>(x, a, e, mus, lvs, (float*)d_out, B, E);
}